// round 8
// baseline (speedup 1.0000x reference)
#include <cuda_runtime.h>
#include <cstddef>

#define NQ     14
#define DIM    16384          // 2^14
#define OUT_N  1000
#define BLK    512
#define NGROUPS (DIM / 4)     // 4096 four-amplitude groups per sweep
#define NGATES  26            // 2 layers * (7 even + 6 odd) fused CZ+RY+RY triples

// RY(theta): y0 = c*x0 - s*x1 ; y1 = s*x0 + c*x1  (x0 = qubit value 0)
__device__ __forceinline__ void apply2(float& x0, float& x1, float c, float s) {
    float y0 = fmaf(c, x0, -s * x1);
    float y1 = fmaf(s, x0,  c * x1);
    x0 = y0; x1 = y1;
}

// One fused two-qubit triple on a 4-amp group.
// m = 2*z_i + z_{i+1}; qubit i = higher bit (p+1), qubit i+1 = lower bit (p).
__device__ __forceinline__ void apply_group(
    float& a00, float& a01, float& a10, float& a11,
    bool first, float cbi, float sbi, float cbj, float sbj,
    float c0, float s0, float c1, float s1)
{
    if (first) {
        // bias RY on qubit i, then qubit i+1 (commute; applied before CZ)
        apply2(a00, a10, cbi, sbi);
        apply2(a01, a11, cbi, sbi);
        apply2(a00, a01, cbj, sbj);
        apply2(a10, a11, cbj, sbj);
    }
    // CZ: flip |11>
    a11 = -a11;
    // RY(weights[l,i,0]) on qubit i
    apply2(a00, a10, c0, s0);
    apply2(a01, a11, c0, s0);
    // RY(weights[l,i,1]) on qubit i+1
    apply2(a00, a01, c1, s1);
    apply2(a10, a11, c1, s1);
}

__global__ __launch_bounds__(BLK, 3)
void qnn_statevec_kernel(const float* __restrict__ input,
                         const float* __restrict__ weights,  // (2, 13, 2)
                         const float* __restrict__ bias,     // (14,)
                         float* __restrict__ out)            // (B, 1000)
{
    extern __shared__ float S[];                 // DIM floats (64 KB)
    __shared__ float gc0[NGATES], gs0[NGATES], gc1[NGATES], gs1[NGATES];
    __shared__ int   gp[NGATES], gi[NGATES];
    __shared__ float cb[NQ], sb[NQ];
    __shared__ float warpsum[BLK / 32];
    __shared__ float s_inv;

    const int tid = threadIdx.x;
    const int b   = blockIdx.x;

    // ---- precompute gate angle params (tiny; cached in L2 across blocks) ----
    if (tid < NGATES) {
        int l, i;
        if (tid < 7)       { l = 0; i = 2 * tid; }
        else if (tid < 13) { l = 0; i = 2 * (tid - 7) + 1; }
        else if (tid < 20) { l = 1; i = 2 * (tid - 13); }
        else               { l = 1; i = 2 * (tid - 20) + 1; }
        float t0 = weights[l * 26 + i * 2 + 0];
        float t1 = weights[l * 26 + i * 2 + 1];
        float c, s;
        sincosf(0.5f * t0, &s, &c); gc0[tid] = c; gs0[tid] = s;
        sincosf(0.5f * t1, &s, &c); gc1[tid] = c; gs1[tid] = s;
        gp[tid] = 12 - i;   // lower bit position of the pair (qubit i+1's bit)
        gi[tid] = i;
    }
    if (tid < NQ) {
        float c, s;
        sincosf(0.5f * bias[tid], &s, &c);
        cb[tid] = c; sb[tid] = s;
    }

    // ---- load row into smem (float4, coalesced) + local sum of squares ----
    const float4* in4 = (const float4*)(input + (size_t)b * DIM);
    float4* S4 = (float4*)S;
    float acc = 0.0f;
#pragma unroll
    for (int k = 0; k < DIM / 4 / BLK; ++k) {    // 8 iters
        int v = tid + k * BLK;
        float4 f = in4[v];
        acc += f.x * f.x + f.y * f.y + f.z * f.z + f.w * f.w;
        S4[v] = f;
    }
#pragma unroll
    for (int o = 16; o; o >>= 1)
        acc += __shfl_xor_sync(0xffffffffu, acc, o);
    if ((tid & 31) == 0) warpsum[tid >> 5] = acc;
    __syncthreads();
    if (tid < BLK / 32) {
        float v = warpsum[tid];
#pragma unroll
        for (int o = (BLK / 32) / 2; o; o >>= 1)
            v += __shfl_xor_sync(0xffffu, v, o);
        if (tid == 0) s_inv = 1.0f / v;          // defer normalization: probs *= 1/||x||^2
    }
    __syncthreads();

    // ---- 26 fused two-qubit gate sweeps ----
#pragma unroll 1
    for (int gate = 0; gate < NGATES; ++gate) {
        const int   p  = gp[gate];
        const float c0 = gc0[gate], s0 = gs0[gate];
        const float c1 = gc1[gate], s1 = gs1[gate];
        const bool  first = (gate < 7);          // fold initial bias layer in
        float cbi = 1.0f, sbi = 0.0f, cbj = 1.0f, sbj = 0.0f;
        if (first) {
            int i = gi[gate];
            cbi = cb[i];     sbi = sb[i];
            cbj = cb[i + 1]; sbj = sb[i + 1];
        }

        if (p == 0) {
            // 4 amps contiguous -> float4, conflict-free
#pragma unroll 4
            for (int g = tid; g < NGROUPS; g += BLK) {
                float4 v = S4[g];
                apply_group(v.x, v.y, v.z, v.w, first,
                            cbi, sbi, cbj, sbj, c0, s0, c1, s1);
                S4[g] = v;
            }
        } else {
            const int stride = 1 << p;
            const int lomask = stride - 1;
#pragma unroll 4
            for (int g = tid; g < NGROUPS; g += BLK) {
                int base = ((g >> p) << (p + 2)) | (g & lomask);
                float a00 = S[base];
                float a01 = S[base + stride];
                float a10 = S[base + 2 * stride];
                float a11 = S[base + 3 * stride];
                apply_group(a00, a01, a10, a11, first,
                            cbi, sbi, cbj, sbj, c0, s0, c1, s1);
                S[base]              = a00;
                S[base + stride]     = a01;
                S[base + 2 * stride] = a10;
                S[base + 3 * stride] = a11;
            }
        }
        __syncthreads();
    }

    // ---- epilogue: probs of last OUT_N basis states, scaled by 1/||x||^2 ----
    const float inv = s_inv;
    float* orow = out + (size_t)b * OUT_N;
#pragma unroll 2
    for (int j = tid; j < OUT_N; j += BLK) {
        float a = S[DIM - OUT_N + j];
        orow[j] = a * a * inv;
    }
}

extern "C" void kernel_launch(void* const* d_in, const int* in_sizes, int n_in,
                              void* d_out, int out_size)
{
    const float* input   = (const float*)d_in[0];   // (B, 16384) f32
    const float* weights = (const float*)d_in[1];   // (2, 13, 2) f32
    const float* bias    = (const float*)d_in[2];   // (14,) f32
    float* out = (float*)d_out;                     // (B, 1000) f32

    const int B = in_sizes[0] / DIM;                // 512

    cudaFuncSetAttribute(qnn_statevec_kernel,
                         cudaFuncAttributeMaxDynamicSharedMemorySize,
                         DIM * (int)sizeof(float));

    qnn_statevec_kernel<<<B, BLK, DIM * sizeof(float)>>>(input, weights, bias, out);
}

// round 9
// speedup vs baseline: 1.0020x; 1.0020x over previous
#include <cuda_runtime.h>
#include <cstddef>

#define NQ     14
#define DIM    16384          // 2^14
#define OUT_N  1000
#define BLK    512
#define NGROUPS (DIM / 4)     // 4096 four-amplitude groups per sweep
#define NGATES  26            // 2 layers * (7 even + 6 odd) fused CZ+RY+RY triples

// RY(theta): y0 = c*x0 - s*x1 ; y1 = s*x0 + c*x1  (x0 = qubit value 0)
__device__ __forceinline__ void apply2(float& x0, float& x1, float c, float s) {
    float y0 = fmaf(c, x0, -s * x1);
    float y1 = fmaf(s, x0,  c * x1);
    x0 = y0; x1 = y1;
}

// One fused two-qubit triple on a 4-amp group.
// m = 2*z_i + z_{i+1}; qubit i = higher bit (p+1), qubit i+1 = lower bit (p).
__device__ __forceinline__ void apply_group(
    float& a00, float& a01, float& a10, float& a11,
    bool first, float cbi, float sbi, float cbj, float sbj,
    float c0, float s0, float c1, float s1)
{
    if (first) {
        // bias RY on qubit i, then qubit i+1 (commute; applied before CZ)
        apply2(a00, a10, cbi, sbi);
        apply2(a01, a11, cbi, sbi);
        apply2(a00, a01, cbj, sbj);
        apply2(a10, a11, cbj, sbj);
    }
    // CZ: flip |11>
    a11 = -a11;
    // RY(weights[l,i,0]) on qubit i
    apply2(a00, a10, c0, s0);
    apply2(a01, a11, c0, s0);
    // RY(weights[l,i,1]) on qubit i+1
    apply2(a00, a01, c1, s1);
    apply2(a10, a11, c1, s1);
}

__global__ __launch_bounds__(BLK, 3)
void qnn_statevec_kernel(const float* __restrict__ input,
                         const float* __restrict__ weights,  // (2, 13, 2)
                         const float* __restrict__ bias,     // (14,)
                         float* __restrict__ out)            // (B, 1000)
{
    extern __shared__ float S[];                 // DIM floats (64 KB)
    __shared__ float gc0[NGATES], gs0[NGATES], gc1[NGATES], gs1[NGATES];
    __shared__ int   gp[NGATES], gi[NGATES];
    __shared__ float cb[NQ], sb[NQ];
    __shared__ float warpsum[BLK / 32];
    __shared__ float s_inv;

    const int tid = threadIdx.x;
    const int b   = blockIdx.x;

    // ---- precompute gate angle params (tiny; cached in L2 across blocks) ----
    if (tid < NGATES) {
        int l, i;
        if (tid < 7)       { l = 0; i = 2 * tid; }
        else if (tid < 13) { l = 0; i = 2 * (tid - 7) + 1; }
        else if (tid < 20) { l = 1; i = 2 * (tid - 13); }
        else               { l = 1; i = 2 * (tid - 20) + 1; }
        float t0 = weights[l * 26 + i * 2 + 0];
        float t1 = weights[l * 26 + i * 2 + 1];
        float c, s;
        sincosf(0.5f * t0, &s, &c); gc0[tid] = c; gs0[tid] = s;
        sincosf(0.5f * t1, &s, &c); gc1[tid] = c; gs1[tid] = s;
        gp[tid] = 12 - i;   // lower bit position of the pair (qubit i+1's bit)
        gi[tid] = i;
    }
    if (tid < NQ) {
        float c, s;
        sincosf(0.5f * bias[tid], &s, &c);
        cb[tid] = c; sb[tid] = s;
    }

    // ---- load row into smem (float4, coalesced) + local sum of squares ----
    const float4* in4 = (const float4*)(input + (size_t)b * DIM);
    float4* S4 = (float4*)S;
    float acc = 0.0f;
#pragma unroll
    for (int k = 0; k < DIM / 4 / BLK; ++k) {    // 8 iters
        int v = tid + k * BLK;
        float4 f = in4[v];
        acc += f.x * f.x + f.y * f.y + f.z * f.z + f.w * f.w;
        S4[v] = f;
    }
#pragma unroll
    for (int o = 16; o; o >>= 1)
        acc += __shfl_xor_sync(0xffffffffu, acc, o);
    if ((tid & 31) == 0) warpsum[tid >> 5] = acc;
    __syncthreads();
    if (tid < BLK / 32) {
        float v = warpsum[tid];
#pragma unroll
        for (int o = (BLK / 32) / 2; o; o >>= 1)
            v += __shfl_xor_sync(0xffffu, v, o);
        if (tid == 0) s_inv = 1.0f / v;          // defer normalization: probs *= 1/||x||^2
    }
    __syncthreads();

    // ---- 26 fused two-qubit gate sweeps ----
#pragma unroll 1
    for (int gate = 0; gate < NGATES; ++gate) {
        const int   p  = gp[gate];
        const float c0 = gc0[gate], s0 = gs0[gate];
        const float c1 = gc1[gate], s1 = gs1[gate];
        const bool  first = (gate < 7);          // fold initial bias layer in
        float cbi = 1.0f, sbi = 0.0f, cbj = 1.0f, sbj = 0.0f;
        if (first) {
            int i = gi[gate];
            cbi = cb[i];     sbi = sb[i];
            cbj = cb[i + 1]; sbj = sb[i + 1];
        }

        if (p == 0) {
            // 4 amps contiguous -> float4, conflict-free
#pragma unroll 4
            for (int g = tid; g < NGROUPS; g += BLK) {
                float4 v = S4[g];
                apply_group(v.x, v.y, v.z, v.w, first,
                            cbi, sbi, cbj, sbj, c0, s0, c1, s1);
                S4[g] = v;
            }
        } else {
            const int stride = 1 << p;
            const int lomask = stride - 1;
#pragma unroll 4
            for (int g = tid; g < NGROUPS; g += BLK) {
                int base = ((g >> p) << (p + 2)) | (g & lomask);
                float a00 = S[base];
                float a01 = S[base + stride];
                float a10 = S[base + 2 * stride];
                float a11 = S[base + 3 * stride];
                apply_group(a00, a01, a10, a11, first,
                            cbi, sbi, cbj, sbj, c0, s0, c1, s1);
                S[base]              = a00;
                S[base + stride]     = a01;
                S[base + 2 * stride] = a10;
                S[base + 3 * stride] = a11;
            }
        }
        __syncthreads();
    }

    // ---- epilogue: probs of last OUT_N basis states, scaled by 1/||x||^2 ----
    const float inv = s_inv;
    float* orow = out + (size_t)b * OUT_N;
#pragma unroll 2
    for (int j = tid; j < OUT_N; j += BLK) {
        float a = S[DIM - OUT_N + j];
        orow[j] = a * a * inv;
    }
}

extern "C" void kernel_launch(void* const* d_in, const int* in_sizes, int n_in,
                              void* d_out, int out_size)
{
    const float* input   = (const float*)d_in[0];   // (B, 16384) f32
    const float* weights = (const float*)d_in[1];   // (2, 13, 2) f32
    const float* bias    = (const float*)d_in[2];   // (14,) f32
    float* out = (float*)d_out;                     // (B, 1000) f32

    const int B = in_sizes[0] / DIM;                // 512

    cudaFuncSetAttribute(qnn_statevec_kernel,
                         cudaFuncAttributeMaxDynamicSharedMemorySize,
                         DIM * (int)sizeof(float));

    qnn_statevec_kernel<<<B, BLK, DIM * sizeof(float)>>>(input, weights, bias, out);
}

// round 10
// speedup vs baseline: 2.0295x; 2.0253x over previous
#include <cuda_runtime.h>
#include <cstddef>

#define DIM   16384
#define OUT_N 1000
#define BLK   512

__device__ __forceinline__ unsigned swz(unsigned a){ return a ^ (((a>>10)&7u)<<2); }

__device__ __forceinline__ void ry(float&x0,float&x1,float c,float s){
    float y0=fmaf(c,x0,-s*x1);
    float y1=fmaf(s,x0, c*x1);
    x0=y0; x1=y1;
}

// Fused CZ + RY(high bit PH) + RY(low bit PL) on a 16-amp register tile.
template<int PH,int PL>
__device__ __forceinline__ void gate2(float r[16], float4 g){
#pragma unroll
    for(int k=0;k<16;++k) if(!((k>>PH)&1) && !((k>>PL)&1)){
        const int k01=k|(1<<PL), k10=k|(1<<PH), k11=k10|(1<<PL);
        float a00=r[k],a01=r[k01],a10=r[k10],a11=-r[k11];   // CZ on |11>
        ry(a00,a10,g.x,g.y); ry(a01,a11,g.x,g.y);           // RY high bit
        ry(a00,a01,g.z,g.w); ry(a10,a11,g.z,g.w);           // RY low bit
        r[k]=a00; r[k01]=a01; r[k10]=a10; r[k11]=a11;
    }
}
template<int P>
__device__ __forceinline__ void bias1(float r[16], float c, float s){
#pragma unroll
    for(int k=0;k<16;++k) if(!((k>>P)&1)) ry(r[k], r[k|(1<<P)], c, s);
}

template<int B3,int B2,int B1,int B0>
__device__ __forceinline__ void ldtile(const float* __restrict__ S, unsigned pb, float r[16]){
#pragma unroll
    for(int k=0;k<16;++k){
        const unsigned off = (unsigned)((((k>>3)&1)<<B3)|(((k>>2)&1)<<B2)|(((k>>1)&1)<<B1)|((k&1)<<B0));
        r[k] = S[pb ^ swz(off)];                    // swz linear: swz(base^off)=swz(base)^swz(off)
    }
}
template<int B3,int B2,int B1,int B0>
__device__ __forceinline__ void sttile(float* __restrict__ S, unsigned pb, const float r[16]){
#pragma unroll
    for(int k=0;k<16;++k){
        const unsigned off = (unsigned)((((k>>3)&1)<<B3)|(((k>>2)&1)<<B2)|(((k>>1)&1)<<B1)|((k&1)<<B0));
        S[pb ^ swz(off)] = r[k];
    }
}

__global__ __launch_bounds__(BLK, 2)
void qnn_kernel(const float* __restrict__ input,
                const float* __restrict__ weights,   // (2,13,2)
                const float* __restrict__ bias,      // (14,)
                float* __restrict__ out)             // (B,1000)
{
    extern __shared__ float S[];                     // DIM floats, swizzled layout
    __shared__ float4 G[26];                         // (c0,s0,c1,s1) per fused gate
    __shared__ float cbit[14], sbit[14];             // bias, indexed by BIT position
    __shared__ float warpsum[BLK/32];
    __shared__ float s_inv;

    const int tid = threadIdx.x;
    const int b   = blockIdx.x;

    // id 0-6: L1 even (i=2*id) -> bits(13-i,12-i); 7-12: L1 odd; 13-19: L2 even; 20-25: L2 odd
    if (tid < 26) {
        int l, i;
        if (tid < 7)       { l=0; i=2*tid; }
        else if (tid < 13) { l=0; i=2*(tid-7)+1; }
        else if (tid < 20) { l=1; i=2*(tid-13); }
        else               { l=1; i=2*(tid-20)+1; }
        float c0,s0,c1,s1;
        sincosf(0.5f*weights[l*26+i*2+0], &s0, &c0);
        sincosf(0.5f*weights[l*26+i*2+1], &s1, &c1);
        G[tid] = make_float4(c0,s0,c1,s1);
    }
    if (tid < 14) {                                  // bit w holds qubit 13-w
        float c,s; sincosf(0.5f*bias[13-tid], &s, &c);
        cbit[tid]=c; sbit[tid]=s;
    }

    // ---- load row (coalesced float4) into swizzled smem + sum of squares ----
    const float4* in4 = (const float4*)(input + (size_t)b*DIM);
    float acc = 0.f;
#pragma unroll
    for (int k=0;k<DIM/4/BLK;++k){
        unsigned v = tid + k*BLK;
        float4 f = in4[v];
        acc += f.x*f.x + f.y*f.y + f.z*f.z + f.w*f.w;
        *(float4*)(S + swz(v<<2)) = f;               // swz keeps bits 0,1 -> aligned
    }
#pragma unroll
    for (int o=16;o;o>>=1) acc += __shfl_xor_sync(~0u, acc, o);
    if ((tid&31)==0) warpsum[tid>>5]=acc;
    __syncthreads();
    if (tid < BLK/32){
        float v = warpsum[tid];
#pragma unroll
        for (int o=(BLK/32)/2;o;o>>=1) v += __shfl_xor_sync(0xffffu, v, o);
        if (!tid) s_inv = 1.f/v;                     // defer normalization to epilogue
    }
    __syncthreads();

    float r[16];

    // S1: bits(13,12,11,10): bias13..10, E1(13,12), E1(11,10), O1(12,11), E2(13,12)
#pragma unroll 1
    for (int it=0; it<2; ++it){
        unsigned idx = tid | (it<<9);
        unsigned pb  = swz(idx);                     // idx0-9 -> a0-a9
        ldtile<13,12,11,10>(S, pb, r);
        bias1<3>(r,cbit[13],sbit[13]); bias1<2>(r,cbit[12],sbit[12]);
        bias1<1>(r,cbit[11],sbit[11]); bias1<0>(r,cbit[10],sbit[10]);
        gate2<3,2>(r,G[0]); gate2<1,0>(r,G[1]); gate2<2,1>(r,G[7]); gate2<3,2>(r,G[13]);
        sttile<13,12,11,10>(S, pb, r);
    }
    __syncthreads();

    // S2: (9,8,7,6): bias9..6, E1(9,8), E1(7,6), O1(8,7)
#pragma unroll 1
    for (int it=0; it<2; ++it){
        unsigned idx = tid | (it<<9);
        unsigned pb  = swz((idx&63u) | ((idx>>6)<<10));
        ldtile<9,8,7,6>(S, pb, r);
        bias1<3>(r,cbit[9],sbit[9]); bias1<2>(r,cbit[8],sbit[8]);
        bias1<1>(r,cbit[7],sbit[7]); bias1<0>(r,cbit[6],sbit[6]);
        gate2<3,2>(r,G[2]); gate2<1,0>(r,G[3]); gate2<2,1>(r,G[9]);
        sttile<9,8,7,6>(S, pb, r);
    }
    __syncthreads();

    // S3: (5,4,3,2): bias5..2, E1(5,4), E1(3,2), O1(4,3)
#pragma unroll 1
    for (int it=0; it<2; ++it){
        unsigned idx = tid | (it<<9);
        unsigned pb  = swz((idx&3u) | (((idx>>2)&7u)<<10) | (((idx>>5)&15u)<<6) | ((idx>>9)<<13));
        ldtile<5,4,3,2>(S, pb, r);
        bias1<3>(r,cbit[5],sbit[5]); bias1<2>(r,cbit[4],sbit[4]);
        bias1<1>(r,cbit[3],sbit[3]); bias1<0>(r,cbit[2],sbit[2]);
        gate2<3,2>(r,G[4]); gate2<1,0>(r,G[5]); gate2<2,1>(r,G[11]);
        sttile<5,4,3,2>(S, pb, r);
    }
    __syncthreads();

    // S4: (3,2,1,0) contiguous, float4: bias1,0, E1(1,0), O1(2,1), E2(1,0)
#pragma unroll 1
    for (int it=0; it<2; ++it){
        unsigned idx  = tid | (it<<9);
        unsigned base = ((idx&3u)<<10) | (((idx>>2)&63u)<<4) | ((idx>>8)<<12);
        unsigned pb   = swz(base);                   // bits 0,1 of pb are 0
#pragma unroll
        for (int m=0;m<4;++m){
            float4 v = *(const float4*)(S + (pb ^ (unsigned)(m<<2)));
            r[4*m]=v.x; r[4*m+1]=v.y; r[4*m+2]=v.z; r[4*m+3]=v.w;
        }
        bias1<1>(r,cbit[1],sbit[1]); bias1<0>(r,cbit[0],sbit[0]);
        gate2<1,0>(r,G[6]); gate2<2,1>(r,G[12]); gate2<1,0>(r,G[19]);
#pragma unroll
        for (int m=0;m<4;++m)
            *(float4*)(S + (pb ^ (unsigned)(m<<2))) =
                make_float4(r[4*m],r[4*m+1],r[4*m+2],r[4*m+3]);
    }
    __syncthreads();

    // S5: (11,10,9,8): O1(10,9), E2(11,10), E2(9,8), O2(10,9)
#pragma unroll 1
    for (int it=0; it<2; ++it){
        unsigned idx = tid | (it<<9);
        unsigned pb  = swz((idx&255u) | ((idx>>8)<<12));
        ldtile<11,10,9,8>(S, pb, r);
        gate2<2,1>(r,G[8]); gate2<3,2>(r,G[14]); gate2<1,0>(r,G[15]); gate2<2,1>(r,G[21]);
        sttile<11,10,9,8>(S, pb, r);
    }
    __syncthreads();

    // S6: (12,11,6,5): O1(6,5), O2(12,11)
#pragma unroll 1
    for (int it=0; it<2; ++it){
        unsigned idx = tid | (it<<9);
        unsigned pb  = swz((idx&31u) | (((idx>>5)&15u)<<7) | ((idx>>9)<<13));
        ldtile<12,11,6,5>(S, pb, r);
        gate2<1,0>(r,G[10]); gate2<3,2>(r,G[20]);
        sttile<12,11,6,5>(S, pb, r);
    }
    __syncthreads();

    // S7: (8,7,6,5): E2(7,6), O2(8,7)
#pragma unroll 1
    for (int it=0; it<2; ++it){
        unsigned idx = tid | (it<<9);
        unsigned pb  = swz((idx&31u) | ((idx>>5)<<9));
        ldtile<8,7,6,5>(S, pb, r);
        gate2<2,1>(r,G[16]); gate2<3,2>(r,G[22]);
        sttile<8,7,6,5>(S, pb, r);
    }
    __syncthreads();

    // S8: (5,4,3,2): E2(5,4), E2(3,2), O2(4,3)
#pragma unroll 1
    for (int it=0; it<2; ++it){
        unsigned idx = tid | (it<<9);
        unsigned pb  = swz((idx&3u) | (((idx>>2)&7u)<<10) | (((idx>>5)&15u)<<6) | ((idx>>9)<<13));
        ldtile<5,4,3,2>(S, pb, r);
        gate2<3,2>(r,G[17]); gate2<1,0>(r,G[18]); gate2<2,1>(r,G[24]);
        sttile<5,4,3,2>(S, pb, r);
    }
    __syncthreads();

    // S9: (6,5,2,1): O2(6,5), O2(2,1)   (2-way bank conflict, accepted)
#pragma unroll 1
    for (int it=0; it<2; ++it){
        unsigned idx  = tid | (it<<9);
        unsigned base = (idx&1u) | (((idx>>1)&1u)<<10) | (((idx>>2)&3u)<<3) | (((idx>>4)&1u)<<7)
                      | (((idx>>5)&3u)<<8) | (((idx>>7)&1u)<<11) | ((idx>>8)<<12);
        unsigned pb   = swz(base);
        ldtile<6,5,2,1>(S, pb, r);
        gate2<3,2>(r,G[23]); gate2<1,0>(r,G[25]);
        sttile<6,5,2,1>(S, pb, r);
    }
    __syncthreads();

    // ---- epilogue: probs of last OUT_N states, scaled by 1/||x||^2 ----
    const float inv = s_inv;
    float* orow = out + (size_t)b*OUT_N;
    for (int j=tid; j<OUT_N; j+=BLK){
        float a = S[swz((unsigned)(DIM-OUT_N+j))];
        orow[j] = a*a*inv;
    }
}

extern "C" void kernel_launch(void* const* d_in, const int* in_sizes, int n_in,
                              void* d_out, int out_size)
{
    const float* input   = (const float*)d_in[0];   // (B,16384) f32
    const float* weights = (const float*)d_in[1];   // (2,13,2)  f32
    const float* bias    = (const float*)d_in[2];   // (14,)     f32
    float* out = (float*)d_out;                     // (B,1000)  f32

    const int B = in_sizes[0] / DIM;                // 512

    cudaFuncSetAttribute(qnn_kernel,
                         cudaFuncAttributeMaxDynamicSharedMemorySize,
                         DIM * (int)sizeof(float));

    qnn_kernel<<<B, BLK, DIM * sizeof(float)>>>(input, weights, bias, out);
}